// round 12
// baseline (speedup 1.0000x reference)
#include <cuda_runtime.h>

#define BATCH   8192
#define BM      64
#define GRID    128
#define NTHR    512
#define TSTEPS  24
#define HDIM    256
#define NCHUNK  4          // 64 h-cols per chunk
#define NKT     8          // tiles per chunk (8 kpp = 32 k each)
#define TPLANE  257        // u128 stride between kpp planes (pad for staging)
#define TILE_T  (8 * TPLANE)   // u128 per tile = 2056 -> 32896 B

#define OFF_A0    0
#define OFF_A1    65536
#define OFF_W     131072          // 2 * 32896 = 65792 -> ends 196864
#define OFF_BIAS  196864          // 4096
#define OFF_WIH   200960          // 8192
#define OFF_TF    209152          // 6144
#define OFF_TM    215296          // 6144
#define OFF_WLR   221440          // 2048
#define OFF_HDOT  223488          // 256
#define OFF_SDOT  223744          // 256
#define OFF_RED   224000          // 256
#define OFF_FLAG  224256          // 16
#define SMEM_BYTES 224272

__device__ float g_cstate[BATCH * HDIM];
__device__ float g_blockSums[GRID];
__device__ unsigned int g_ctr;

__device__ __forceinline__ void ffma2(unsigned long long& acc,
                                      unsigned long long a,
                                      unsigned long long b) {
    asm volatile("fma.rn.f32x2 %0, %1, %2, %0;" : "+l"(acc) : "l"(a), "l"(b));
}
__device__ __forceinline__ float2 up64(unsigned long long v) {
    float2 r;
    asm("mov.b64 {%0, %1}, %2;" : "=f"(r.x), "=f"(r.y) : "l"(v));
    return r;
}
__device__ __forceinline__ float sigm(float x) { return 1.f / (1.f + __expf(-x)); }
__device__ __forceinline__ float tanh_f(float x) { return 1.f - 2.f / (__expf(2.f * x) + 1.f); }

__device__ __forceinline__ void cp16(void* smem_dst, const void* gsrc) {
    unsigned int d = (unsigned int)__cvta_generic_to_shared(smem_dst);
    asm volatile("cp.async.cg.shared.global [%0], [%1], 16;" :: "r"(d), "l"(gsrc));
}

// Stage one LSTM W tile: 256 wrows (g*64+col) x 8 kpp, u128 = 4 consecutive k-floats.
// dst layout: [kpp][wrow] u128 with plane stride TPLANE.
__device__ __forceinline__ void issue_w_lstm(const float* __restrict__ Whh,
                                             int c, int kt,
                                             ulonglong2* dst, int tid) {
#pragma unroll
    for (int i = 0; i < 4; i++) {
        int lin = i * 512 + tid;          // 0..2047
        int wrow = lin >> 3;              // 0..255 = g*64 + cl
        int kpp  = lin & 7;
        int g = wrow >> 6, cl = wrow & 63;
        const float* src = Whh + (((g << 8) + (c << 6) + cl) << 8) + (kt << 5) + (kpp << 2);
        cp16(dst + kpp * TPLANE + wrow, src);
    }
}

// Stage one MLP W tile: 64 wrows (out-cols of chunk) x 8 kpp.
__device__ __forceinline__ void issue_w_mlp(const float* __restrict__ W,
                                            int c, int kt,
                                            ulonglong2* dst, int tid) {
    int wrow = tid >> 3;                  // 0..63
    int kpp  = tid & 7;
    const float* src = W + (((c << 6) + wrow) << 8) + (kt << 5) + (kpp << 2);
    cp16(dst + kpp * TPLANE + wrow, src);
}

// MLP layer: out[r][n] = relu(in . W[n] + b[n]); 4 chunks of 64 out-cols.
__device__ __forceinline__ void mlp_layer(const float* __restrict__ in,
                                          float* __restrict__ outb,
                                          const float* __restrict__ W,
                                          const float* __restrict__ bias,
                                          ulonglong2* Wbuf,
                                          int tid, int tx, int rg, int wc) {
    const ulonglong2* Au = (const ulonglong2*)in;
    const int rbase = rg << 3;
#pragma unroll 1
    for (int c = 0; c < 4; c++) {
        unsigned long long acc[8];
#pragma unroll
        for (int v = 0; v < 8; v++) acc[v] = 0ull;

        issue_w_mlp(W, c, 0, Wbuf, tid);
        asm volatile("cp.async.commit_group;");
#pragma unroll 1
        for (int kt = 0; kt < 8; kt++) {
            asm volatile("cp.async.wait_group 0;");
            __syncthreads();
            if (kt + 1 < 8) {
                issue_w_mlp(W, c, kt + 1, Wbuf + ((kt + 1) & 1) * TILE_T, tid);
                asm volatile("cp.async.commit_group;");
            }
            const ulonglong2* Wt = Wbuf + (kt & 1) * TILE_T;
#pragma unroll 1
            for (int kpp = 0; kpp < 8; kpp++) {
                ulonglong2 a[8];
#pragma unroll
                for (int v = 0; v < 8; v++) a[v] = Au[(rbase + v) * 64 + (kt << 3) + kpp];
                ulonglong2 b = Wt[kpp * TPLANE + (wc << 5) + tx];
#pragma unroll
                for (int v = 0; v < 8; v++) { ffma2(acc[v], a[v].x, b.x); ffma2(acc[v], a[v].y, b.y); }
            }
            __syncthreads();
        }
        int n = (c << 6) + (wc << 5) + tx;
        float bb = bias[n];
#pragma unroll
        for (int v = 0; v < 8; v++) {
            float2 p = up64(acc[v]);
            outb[(rbase + v) * HDIM + n] = fmaxf(p.x + p.y + bb, 0.f);
        }
        __syncthreads();
    }
}

__device__ __forceinline__ void dot256_512(const float* __restrict__ buf,
                                           const float* __restrict__ w,
                                           float* __restrict__ outv, int tid) {
    int r = tid >> 3, q = tid & 7;        // 8 threads per row, 32 f32 each
    const float4* hv = (const float4*)(buf + r * HDIM + q * 32);
    const float4* wv = (const float4*)(w + q * 32);
    float s = 0.f;
#pragma unroll
    for (int i = 0; i < 8; i++) {
        float4 a = hv[i], b = wv[i];
        s += a.x * b.x + a.y * b.y + a.z * b.z + a.w * b.w;
    }
    s += __shfl_xor_sync(0xffffffffu, s, 1);
    s += __shfl_xor_sync(0xffffffffu, s, 2);
    s += __shfl_xor_sync(0xffffffffu, s, 4);
    if (q == 0) outv[r] = s;
}

__global__ void __launch_bounds__(NTHR, 1)
fused_kernel(const float* __restrict__ statf, const float* __restrict__ tf,
             const float* __restrict__ tm, const float* __restrict__ tgt,
             const float* __restrict__ h0, const float* __restrict__ c0,
             const float* __restrict__ Wih, const float* __restrict__ Whh,
             const float* __restrict__ bih, const float* __restrict__ bhh,
             const float* __restrict__ W1, const float* __restrict__ b1,
             const float* __restrict__ W2, const float* __restrict__ b2p,
             const float* __restrict__ W3, const float* __restrict__ b3,
             const float* __restrict__ Wlr, const float* __restrict__ blr,
             float* __restrict__ out) {
    extern __shared__ __align__(16) char smem[];
    const int tid = threadIdx.x;
    const int tx = tid & 31;
    const int wid = tid >> 5;
    const int rg = wid >> 1;              // row-group 0..7 (8 rows each)
    const int wc = wid & 1;               // column half
    const int r0 = blockIdx.x * BM;
    const int rbase = rg << 3;

    float* A0   = (float*)(smem + OFF_A0);
    float* A1   = (float*)(smem + OFF_A1);
    ulonglong2* Wbuf = (ulonglong2*)(smem + OFF_W);
    float* sBias = (float*)(smem + OFF_BIAS);
    float* sWih  = (float*)(smem + OFF_WIH);
    float* sTF   = (float*)(smem + OFF_TF);
    float* sTM   = (float*)(smem + OFF_TM);
    float* sWlr  = (float*)(smem + OFF_WLR);
    float* sHdot = (float*)(smem + OFF_HDOT);
    float* sSdot = (float*)(smem + OFF_SDOT);
    float* sRed  = (float*)(smem + OFF_RED);
    int*   sFlag = (int*)(smem + OFF_FLAG);

#pragma unroll
    for (int i = 0; i < 2; i++) { int k = tid + i * 512; sBias[k] = bih[k] + bhh[k]; }
#pragma unroll
    for (int i = 0; i < 4; i++) { int k = tid + i * 512; sWih[k] = Wih[k]; }
#pragma unroll
    for (int i = 0; i < 3; i++) { int k = tid + i * 512; sTF[k] = tf[r0 * 24 + k]; sTM[k] = tm[r0 * 24 + k]; }
    if (tid < 512) sWlr[tid] = Wlr[tid];
    {
        float4* dst = (float4*)A0;
        const float4* src = (const float4*)(h0 + (long)r0 * HDIM);
#pragma unroll
        for (int i = 0; i < 8; i++) dst[tid + i * 512] = src[tid + i * 512];
    }
    __syncthreads();

    float* Acur = A0;
    float* Anext = A1;

    // prime the W-tile ring
    issue_w_lstm(Whh, 0, 0, Wbuf, tid);
    asm volatile("cp.async.commit_group;");

#pragma unroll 1
    for (int t = 0; t < TSTEPS; t++) {
        const ulonglong2* Au = (const ulonglong2*)Acur;
#pragma unroll 1
        for (int c = 0; c < NCHUNK; c++) {          // 64 h-cols per chunk
            unsigned long long acc[8][4];
#pragma unroll
            for (int v = 0; v < 8; v++)
#pragma unroll
                for (int g = 0; g < 4; g++) acc[v][g] = 0ull;

            const int jg = (c << 6) + (wc << 5) + tx;
            float cold[8];
            {
                const float* csrc = (t == 0) ? c0 : g_cstate;
#pragma unroll
                for (int v = 0; v < 8; v++)
                    cold[v] = csrc[(r0 + rbase + v) * HDIM + jg];
            }

#pragma unroll 1
            for (int kt = 0; kt < NKT; kt++) {
                asm volatile("cp.async.wait_group 0;");
                __syncthreads();
                // issue next tile in the global ring (W is h-independent)
                {
                    int nkt = kt + 1, nc = c;
                    if (nkt == NKT) { nkt = 0; nc = c + 1; if (nc == NCHUNK) nc = 0; }
                    bool last = (t == TSTEPS - 1) && (c == NCHUNK - 1) && (kt == NKT - 1);
                    if (!last) {
                        issue_w_lstm(Whh, nc, nkt, Wbuf + ((kt + 1) & 1) * TILE_T, tid);
                        asm volatile("cp.async.commit_group;");
                    }
                }
                const ulonglong2* Wt = Wbuf + (kt & 1) * TILE_T;
#pragma unroll 1
                for (int kpp = 0; kpp < 8; kpp++) {
                    ulonglong2 a[8];
#pragma unroll
                    for (int v = 0; v < 8; v++)
                        a[v] = Au[(rbase + v) * 64 + (kt << 3) + kpp];
                    const ulonglong2* Bp = Wt + kpp * TPLANE + (wc << 5) + tx;
#pragma unroll
                    for (int g = 0; g < 4; g++) {
                        ulonglong2 b = Bp[g << 6];
#pragma unroll
                        for (int v = 0; v < 8; v++) {
                            ffma2(acc[v][g], a[v].x, b.x);
                            ffma2(acc[v][g], a[v].y, b.y);
                        }
                    }
                }
            }
            // gate nonlinearity + state update (col jg, rows rbase..rbase+7)
#pragma unroll
            for (int v = 0; v < 8; v++) {
                int r = rbase + v;
                float xv = sTF[r * 24 + t], mv = sTM[r * 24 + t];
                float gate[4];
#pragma unroll
                for (int g = 0; g < 4; g++) {
                    int row = (g << 8) + jg;
                    float2 p = up64(acc[v][g]);
                    gate[g] = p.x + p.y + sBias[row]
                            + xv * sWih[row * 2] + mv * sWih[row * 2 + 1];
                }
                float iv = sigm(gate[0]);
                float fv = sigm(gate[1]);
                float gv = tanh_f(gate[2]);
                float ov = sigm(gate[3]);
                float cn = fv * cold[v] + iv * gv;
                g_cstate[(r0 + r) * HDIM + jg] = cn;
                Anext[r * HDIM + jg] = ov * tanh_f(cn);
            }
        }
        { float* tsw = Acur; Acur = Anext; Anext = tsw; }
    }
    __syncthreads();

    dot256_512(Acur, sWlr, sHdot, tid);
    __syncthreads();

    {
        float4* dst = (float4*)Acur;
        const float4* src = (const float4*)(statf + (long)r0 * HDIM);
#pragma unroll
        for (int i = 0; i < 8; i++) dst[tid + i * 512] = src[tid + i * 512];
    }
    __syncthreads();

    mlp_layer(Acur, Anext, W1, b1, Wbuf, tid, tx, rg, wc);
    mlp_layer(Anext, Acur, W2, b2p, Wbuf, tid, tx, rg, wc);
    mlp_layer(Acur, Anext, W3, b3, Wbuf, tid, tx, rg, wc);

    dot256_512(Anext, sWlr + 256, sSdot, tid);
    __syncthreads();

    if (tid < BM) {
        int r = tid;
        float p = sHdot[r] + sSdot[r] + blr[0];
        out[r0 + r] = p;
        float tg = tgt[r0 + r];
        sRed[r] = fmaxf(p, 0.f) - p * tg + log1pf(expf(-fabsf(p)));
    }
    __syncthreads();
    if (tid < 32) {
        float s = sRed[tid] + sRed[tid + 32];
#pragma unroll
        for (int o = 16; o > 0; o >>= 1) s += __shfl_down_sync(0xffffffffu, s, o);
        if (tid == 0) g_blockSums[blockIdx.x] = s;
    }

    // last-CTA-done: final loss reduction
    __threadfence();
    if (tid == 0) {
        unsigned int n = atomicAdd(&g_ctr, 1u);
        sFlag[0] = (n == GRID - 1) ? 1 : 0;
    }
    __syncthreads();
    if (sFlag[0]) {
        float v = 0.f;
        if (tid < GRID) v = ((volatile float*)g_blockSums)[tid];
        float s = v;
#pragma unroll
        for (int o = 16; o > 0; o >>= 1) s += __shfl_down_sync(0xffffffffu, s, o);
        if ((tid & 31) == 0 && tid < GRID) sRed[tid >> 5] = s;
        __syncthreads();
        if (tid == 0) {
            float tot = sRed[0] + sRed[1] + sRed[2] + sRed[3];
            out[BATCH] = tot * (1.0f / (float)BATCH);
            g_ctr = 0;
        }
    }
}

extern "C" void kernel_launch(void* const* d_in, const int* in_sizes, int n_in,
                              void* d_out, int out_size) {
    cudaFuncSetAttribute(fused_kernel, cudaFuncAttributeMaxDynamicSharedMemorySize, SMEM_BYTES);
    const float* statf = (const float*)d_in[0];
    const float* tf    = (const float*)d_in[1];
    const float* tm    = (const float*)d_in[2];
    const float* tgt   = (const float*)d_in[3];
    const float* h0    = (const float*)d_in[4];
    const float* c0    = (const float*)d_in[5];
    const float* Wih   = (const float*)d_in[6];
    const float* Whh   = (const float*)d_in[7];
    const float* bih   = (const float*)d_in[8];
    const float* bhh   = (const float*)d_in[9];
    const float* W1    = (const float*)d_in[10];
    const float* b1    = (const float*)d_in[11];
    const float* W2    = (const float*)d_in[12];
    const float* b2    = (const float*)d_in[13];
    const float* W3    = (const float*)d_in[14];
    const float* b3    = (const float*)d_in[15];
    const float* Wlr   = (const float*)d_in[16];
    const float* blr   = (const float*)d_in[17];
    float* out = (float*)d_out;

    fused_kernel<<<GRID, NTHR, SMEM_BYTES>>>(statf, tf, tm, tgt, h0, c0,
                                             Wih, Whh, bih, bhh,
                                             W1, b1, W2, b2, W3, b3,
                                             Wlr, blr, out);
}